// round 8
// baseline (speedup 1.0000x reference)
#include <cuda_runtime.h>
#include <cuda.h>
#include <cuda_fp16.h>
#include <cstdint>

// ============================================================================
// Problem constants
// ============================================================================
#define DIN    4096
#define DOUT   12288
#define MROWS  4096

#define BM     256              // 4 warp-rows x 64
#define BN     192              // 3 warp-cols x 64
#define BK     64               // halves per stage-k = 128 bytes per row
#define STAGES 4
#define KT     (DIN / BK)       // 64

#define A_BYTES     (BM * 128)              // 32768
#define B_BYTES     (BN * 128)              // 24576
#define STAGE_BYTES (A_BYTES + B_BYTES)     // 57344
#define SMEM_DATA0  1024
#define SMEM_TOTAL  (SMEM_DATA0 + STAGES * STAGE_BYTES)   // 230400 (< 232448 opt-in)

#define MBAR_FULL(s)  ((s) * 16)
#define MBAR_EMPTY(s) ((s) * 16 + 8)

#define NWARPS_C 12                      // compute warps (warp tile 64x64)
#define NTHREADS (NWARPS_C * 32 + 32)    // +1 producer warp = 416

// ============================================================================
// Scratch: fp16 operands (dequantized W, converted X)
// ============================================================================
__device__ __half g_W16[(size_t)DOUT * DIN];   // 96 MB
__device__ __half g_X16[(size_t)MROWS * DIN];  // 32 MB

// ============================================================================
// PTX helpers
// ============================================================================
__device__ __forceinline__ uint32_t smem_u32(const void* p) {
    uint32_t a;
    asm("{ .reg .u64 t; cvta.to.shared.u64 t, %1; cvt.u32.u64 %0, t; }" : "=r"(a) : "l"(p));
    return a;
}
__device__ __forceinline__ uint32_t elect_one() {
    uint32_t p;
    asm volatile("{ .reg .pred p; elect.sync _|p, 0xFFFFFFFF; selp.b32 %0, 1, 0, p; }" : "=r"(p));
    return p;
}

#define MBAR_INIT(addr, cnt) \
    asm volatile("mbarrier.init.shared.b64 [%0], %1;" :: "r"(addr), "r"(cnt) : "memory")
#define MBAR_EXPECT_TX(addr, bytes) \
    asm volatile("mbarrier.arrive.expect_tx.shared.b64 _, [%0], %1;" :: "r"(addr), "r"(bytes) : "memory")
#define MBAR_ARRIVE(addr) \
    asm volatile("mbarrier.arrive.shared.b64 _, [%0];" :: "r"(addr) : "memory")

#define MBAR_WAIT(mbar_addr, phase_parity) do {                                         \
    uint32_t _mbar = (uint32_t)(mbar_addr);                                             \
    uint32_t _par  = (uint32_t)(phase_parity);                                          \
    uint32_t _done;                                                                     \
    asm volatile("{\n\t.reg .pred p;\n\t"                                               \
        "mbarrier.try_wait.parity.acquire.cta.shared::cta.b64 p, [%1], %2;\n\t"         \
        "selp.b32 %0, 1, 0, p;\n\t}"                                                    \
        : "=r"(_done) : "r"(_mbar), "r"(_par) : "memory");                              \
    if (!_done) {                                                                       \
        asm volatile("{\n\t.reg .pred P1;\n\t"                                          \
            "WAIT_LOOP_%=:\n\t"                                                         \
            "mbarrier.try_wait.parity.acquire.cta.shared::cta.b64 P1, [%0], %1, 0x989680;\n\t" \
            "@P1 bra.uni WAIT_DONE_%=;\n\t"                                             \
            "bra.uni WAIT_LOOP_%=;\n\t"                                                 \
            "WAIT_DONE_%=:\n\t}"                                                        \
            :: "r"(_mbar), "r"(_par) : "memory");                                       \
    }                                                                                   \
} while (0)

#define TMA_LOAD2D(smem, map, cx, cy, mbar)                                             \
    asm volatile("cp.async.bulk.tensor.2d.shared::cta.global.tile.mbarrier::complete_tx::bytes " \
                 "[%0], [%1, {%2, %3}], [%4];"                                          \
                 :: "r"(smem), "l"(map), "r"(cx), "r"(cy), "r"(mbar) : "memory")

#define LDSM_X4(r0, r1, r2, r3, addr)                                                   \
    asm volatile("ldmatrix.sync.aligned.m8n8.x4.shared.b16 {%0,%1,%2,%3}, [%4];"        \
                 : "=r"(r0), "=r"(r1), "=r"(r2), "=r"(r3) : "r"(addr))

__device__ __forceinline__ void mma_f16(float c[4], uint32_t a0, uint32_t a1, uint32_t a2,
                                        uint32_t a3, uint32_t b0, uint32_t b1) {
    asm volatile(
        "mma.sync.aligned.m16n8k16.row.col.f32.f16.f16.f32 "
        "{%0,%1,%2,%3}, {%4,%5,%6,%7}, {%8,%9}, {%0,%1,%2,%3};"
        : "+f"(c[0]), "+f"(c[1]), "+f"(c[2]), "+f"(c[3])
        : "r"(a0), "r"(a1), "r"(a2), "r"(a3), "r"(b0), "r"(b1));
}

// ============================================================================
// Merged prep: dequant W -> fp16, convert X -> fp16 (one launch; R4-validated)
// ============================================================================
__device__ __forceinline__ uint32_t h2bits(float a, float b) {
    __half2 h = __floats2half2_rn(a, b);
    return *reinterpret_cast<uint32_t*>(&h);
}

#define W_BLOCKS ((DOUT * DIN / 8) / 256)   // 24576
#define X_BLOCKS ((MROWS * DIN / 8) / 256)  // 8192

__global__ void prep_kernel(const float4* __restrict__ x, const float4* __restrict__ peso,
                            const float* __restrict__ escala,
                            uint4* __restrict__ gX, uint4* __restrict__ gW) {
    const int bid = blockIdx.x;
    if (bid < W_BLOCKS) {
        int i = bid * 256 + threadIdx.x;
        int e   = i << 3;
        int row = e >> 12;            // / DIN
        int col = e & (DIN - 1);
        float s = __ldg(&escala[(row >> 7) * (DIN / 128) + (col >> 7)]);
        float4 v0 = peso[2 * i], v1 = peso[2 * i + 1];
        uint4 u;
        u.x = h2bits(v0.x * s, v0.y * s); u.y = h2bits(v0.z * s, v0.w * s);
        u.z = h2bits(v1.x * s, v1.y * s); u.w = h2bits(v1.z * s, v1.w * s);
        gW[i] = u;
    } else {
        int i = (bid - W_BLOCKS) * 256 + threadIdx.x;
        float4 v0 = x[2 * i], v1 = x[2 * i + 1];
        uint4 u;
        u.x = h2bits(v0.x, v0.y); u.y = h2bits(v0.z, v0.w);
        u.z = h2bits(v1.x, v1.y); u.w = h2bits(v1.z, v1.w);
        gX[i] = u;
    }
}

// ============================================================================
// GEMM: C[m,n] = sum_k X[m,k] * W[n,k]   (fp16 in, fp32 accum/out)
//   CTA 256x192, BK=64, 4-stage TMA ring (R3-validated protocol), occ 1.
//   12 compute warps (4M x 3N grid, warp tile 64x64) + 1 TMA producer warp.
//   64x64 warp tile maximizes FLOP per LDS byte (mn/(m+n)): smem crossbar
//   demand drops from ~100% (R7 profile: L1=87.5%) to ~50%.
// ============================================================================
__global__ void __launch_bounds__(NTHREADS, 1)
gemm_f16_kernel(const __grid_constant__ CUtensorMap tmA,
                const __grid_constant__ CUtensorMap tmB,
                float* __restrict__ out) {
    extern __shared__ char smem[];
    const uint32_t sb = smem_u32(smem);
    const int tid  = threadIdx.x;
    const int wid  = tid >> 5;
    const int lane = tid & 31;

    const int m0 = blockIdx.y * BM;
    const int n0 = blockIdx.x * BN;

    if (tid == 0) {
        for (int s = 0; s < STAGES; s++) {
            MBAR_INIT(sb + MBAR_FULL(s), 1);
            MBAR_INIT(sb + MBAR_EMPTY(s), NWARPS_C);
        }
    }
    __syncthreads();

    if (wid == NWARPS_C) {
        // ---------------- TMA producer warp ----------------
        if (elect_one()) {
            int s = 0, ph = 1;               // first STAGES empty-waits pass immediately
            for (int kt = 0; kt < KT; kt++) {
                MBAR_WAIT(sb + MBAR_EMPTY(s), ph);
                MBAR_EXPECT_TX(sb + MBAR_FULL(s), STAGE_BYTES);
                const uint32_t stg = sb + SMEM_DATA0 + s * STAGE_BYTES;
                TMA_LOAD2D(stg,           &tmA, kt * BK, m0, sb + MBAR_FULL(s));
                TMA_LOAD2D(stg + A_BYTES, &tmB, kt * BK, n0, sb + MBAR_FULL(s));
                if (s == STAGES - 1) { s = 0; ph ^= 1; } else { s++; }
            }
        }
        return;
    }

    // ---------------- compute warps: 4M x 3N grid, warp tile 64x64 ----------------
    const int warp_m = wid & 3;          // 0..3 -> M offset 64*warp_m
    const int warp_n = wid >> 2;         // 0..2 -> N offset 64*warp_n
    const int q  = lane >> 3;            // ldmatrix quad
    const int iq = lane & 7;

    const int a_rif  = ((q & 1) << 3) + iq;    // row within 16-row fragment
    const int a_csel = q >> 1;                 // 16B chunk select
    const int b_rif  = ((q >> 1) << 3) + iq;
    const int b_csel = q & 1;

    float c[4][8][4];
#pragma unroll
    for (int mf = 0; mf < 4; mf++)
#pragma unroll
        for (int nf = 0; nf < 8; nf++)
#pragma unroll
            for (int r = 0; r < 4; r++) c[mf][nf][r] = 0.0f;

    // row-invariant address components
    uint32_t a_off[4], a_sw[4], b_off[4], b_sw[4];
#pragma unroll
    for (int mf = 0; mf < 4; mf++) {
        int row = warp_m * 64 + mf * 16 + a_rif;
        a_off[mf] = (uint32_t)(row * 128);
        a_sw[mf]  = (uint32_t)(row & 7);
    }
#pragma unroll
    for (int p = 0; p < 4; p++) {
        int row = warp_n * 64 + p * 16 + b_rif;
        b_off[p] = (uint32_t)(row * 128);
        b_sw[p]  = (uint32_t)(row & 7);
    }

    int s = 0, ph = 0;
    for (int kt = 0; kt < KT; kt++) {
        MBAR_WAIT(sb + MBAR_FULL(s), ph);
        const uint32_t As = sb + SMEM_DATA0 + s * STAGE_BYTES;
        const uint32_t Bs = As + A_BYTES;

#pragma unroll
        for (int ks = 0; ks < 4; ks++) {       // 4 x k16 per stage
            uint32_t a[4][4], b[8][2];
#pragma unroll
            for (int mf = 0; mf < 4; mf++) {
                uint32_t ch = (uint32_t)(2 * ks + a_csel);
                LDSM_X4(a[mf][0], a[mf][1], a[mf][2], a[mf][3],
                        As + a_off[mf] + ((ch ^ a_sw[mf]) << 4));
            }
#pragma unroll
            for (int p = 0; p < 4; p++) {
                uint32_t ch = (uint32_t)(2 * ks + b_csel);
                LDSM_X4(b[2 * p][0], b[2 * p][1], b[2 * p + 1][0], b[2 * p + 1][1],
                        Bs + b_off[p] + ((ch ^ b_sw[p]) << 4));
            }
#pragma unroll
            for (int mf = 0; mf < 4; mf++)
#pragma unroll
                for (int nf = 0; nf < 8; nf++)
                    mma_f16(c[mf][nf], a[mf][0], a[mf][1], a[mf][2], a[mf][3],
                            b[nf][0], b[nf][1]);
        }
        // Safe point: all this stage's LDSM results consumed by mma.sync.
        __syncwarp();
        if (lane == 0) MBAR_ARRIVE(sb + MBAR_EMPTY(s));
        if (s == STAGES - 1) { s = 0; ph ^= 1; } else { s++; }
    }

    // ---------------- epilogue: direct float2 stores ----------------
    const int g   = lane >> 2;
    const int tig = lane & 3;
#pragma unroll
    for (int mf = 0; mf < 4; mf++) {
        const int m = m0 + warp_m * 64 + mf * 16 + g;
#pragma unroll
        for (int nf = 0; nf < 8; nf++) {
            const int n = n0 + warp_n * 64 + nf * 8 + tig * 2;
            *reinterpret_cast<float2*>(&out[(size_t)m * DOUT + n]) =
                make_float2(c[mf][nf][0], c[mf][nf][1]);
            *reinterpret_cast<float2*>(&out[(size_t)(m + 8) * DOUT + n]) =
                make_float2(c[mf][nf][2], c[mf][nf][3]);
        }
    }
}

// ============================================================================
// Host launch
// ============================================================================
typedef CUresult (*PFN_encodeTiled)(CUtensorMap*, CUtensorMapDataType, cuuint32_t, void*,
                                    const cuuint64_t*, const cuuint64_t*, const cuuint32_t*,
                                    const cuuint32_t*, CUtensorMapInterleave, CUtensorMapSwizzle,
                                    CUtensorMapL2promotion, CUtensorMapFloatOOBfill);

static PFN_encodeTiled get_encode_fn() {
    void* fn = nullptr;
#if CUDART_VERSION >= 12050
    cudaDriverEntryPointQueryResult qr;
    cudaGetDriverEntryPointByVersion("cuTensorMapEncodeTiled", &fn, 12000, cudaEnableDefault, &qr);
#else
    cudaGetDriverEntryPoint("cuTensorMapEncodeTiled", &fn, cudaEnableDefault);
#endif
    return (PFN_encodeTiled)fn;
}

static void encode_2d_f16(PFN_encodeTiled enc, CUtensorMap* tm, void* ptr,
                          uint64_t d0, uint64_t d1, uint32_t b0, uint32_t b1) {
    cuuint64_t dims[2]    = {d0, d1};
    cuuint64_t strides[1] = {d0 * sizeof(__half)};
    cuuint32_t box[2]     = {b0, b1};
    cuuint32_t es[2]      = {1, 1};
    enc(tm, CU_TENSOR_MAP_DATA_TYPE_FLOAT16, 2, ptr, dims, strides, box, es,
        CU_TENSOR_MAP_INTERLEAVE_NONE, CU_TENSOR_MAP_SWIZZLE_128B,
        CU_TENSOR_MAP_L2_PROMOTION_L2_128B, CU_TENSOR_MAP_FLOAT_OOB_FILL_NONE);
}

extern "C" void kernel_launch(void* const* d_in, const int* in_sizes, int n_in,
                              void* d_out, int out_size) {
    const float* x      = (const float*)d_in[0];
    const float* peso   = (const float*)d_in[1];
    const float* escala = (const float*)d_in[2];
    float* out          = (float*)d_out;

    __half *gX = nullptr, *gW = nullptr;
    cudaGetSymbolAddress((void**)&gX, g_X16);
    cudaGetSymbolAddress((void**)&gW, g_W16);

    prep_kernel<<<W_BLOCKS + X_BLOCKS, 256>>>((const float4*)x, (const float4*)peso, escala,
                                              (uint4*)gX, (uint4*)gW);

    PFN_encodeTiled enc = get_encode_fn();
    CUtensorMap tmA, tmB;
    encode_2d_f16(enc, &tmA, gX, DIN, MROWS, BK, BM);   // box 64x256
    encode_2d_f16(enc, &tmB, gW, DIN, DOUT,  BK, BN);   // box 64x192

    static bool attr_set = false;
    if (!attr_set) {
        cudaFuncSetAttribute(gemm_f16_kernel, cudaFuncAttributeMaxDynamicSharedMemorySize,
                             SMEM_TOTAL);
        attr_set = true;
    }

    dim3 grid(DOUT / BN, MROWS / BM);   // 64 x 16
    gemm_f16_kernel<<<grid, NTHREADS, SMEM_TOTAL>>>(tmA, tmB, out);
}

// round 9
// speedup vs baseline: 3.4534x; 3.4534x over previous
#include <cuda_runtime.h>
#include <cuda.h>
#include <cuda_fp16.h>
#include <cstdint>

// ============================================================================
// Problem constants   (R4-passing shape: 256x128, 8x 64x64 warps, 288 thr)
// ============================================================================
#define DIN    4096
#define DOUT   12288
#define MROWS  4096

#define BM     256
#define BN     128
#define BK     64               // halves per stage-k = 128 bytes per row
#define STAGES 4
#define KT     (DIN / BK)       // 64

#define A_BYTES     (BM * 128)              // 32768
#define B_BYTES     (BN * 128)              // 16384
#define STAGE_BYTES (A_BYTES + B_BYTES)     // 49152
#define SMEM_DATA0  1024
#define SMEM_TOTAL  (SMEM_DATA0 + STAGES * STAGE_BYTES)   // 197632

#define MBAR_FULL(s)  ((s) * 16)
#define MBAR_EMPTY(s) ((s) * 16 + 8)

#define NWARPS_C 8                       // compute warps (warp tile 64x64)
#define NTHREADS (NWARPS_C * 32 + 32)    // +1 producer warp = 288  (reg cap 227)

// ============================================================================
// Scratch: fp16 operands (dequantized W, converted X)
// ============================================================================
__device__ __half g_W16[(size_t)DOUT * DIN];   // 96 MB
__device__ __half g_X16[(size_t)MROWS * DIN];  // 32 MB

// ============================================================================
// PTX helpers
// ============================================================================
__device__ __forceinline__ uint32_t smem_u32(const void* p) {
    uint32_t a;
    asm("{ .reg .u64 t; cvta.to.shared.u64 t, %1; cvt.u32.u64 %0, t; }" : "=r"(a) : "l"(p));
    return a;
}
__device__ __forceinline__ uint32_t elect_one() {
    uint32_t p;
    asm volatile("{ .reg .pred p; elect.sync _|p, 0xFFFFFFFF; selp.b32 %0, 1, 0, p; }" : "=r"(p));
    return p;
}

#define MBAR_INIT(addr, cnt) \
    asm volatile("mbarrier.init.shared.b64 [%0], %1;" :: "r"(addr), "r"(cnt) : "memory")
#define MBAR_EXPECT_TX(addr, bytes) \
    asm volatile("mbarrier.arrive.expect_tx.shared.b64 _, [%0], %1;" :: "r"(addr), "r"(bytes) : "memory")
#define MBAR_ARRIVE(addr) \
    asm volatile("mbarrier.arrive.shared.b64 _, [%0];" :: "r"(addr) : "memory")

#define MBAR_WAIT(mbar_addr, phase_parity) do {                                         \
    uint32_t _mbar = (uint32_t)(mbar_addr);                                             \
    uint32_t _par  = (uint32_t)(phase_parity);                                          \
    uint32_t _done;                                                                     \
    asm volatile("{\n\t.reg .pred p;\n\t"                                               \
        "mbarrier.try_wait.parity.acquire.cta.shared::cta.b64 p, [%1], %2;\n\t"         \
        "selp.b32 %0, 1, 0, p;\n\t}"                                                    \
        : "=r"(_done) : "r"(_mbar), "r"(_par) : "memory");                              \
    if (!_done) {                                                                       \
        asm volatile("{\n\t.reg .pred P1;\n\t"                                          \
            "WAIT_LOOP_%=:\n\t"                                                         \
            "mbarrier.try_wait.parity.acquire.cta.shared::cta.b64 P1, [%0], %1, 0x989680;\n\t" \
            "@P1 bra.uni WAIT_DONE_%=;\n\t"                                             \
            "bra.uni WAIT_LOOP_%=;\n\t"                                                 \
            "WAIT_DONE_%=:\n\t}"                                                        \
            :: "r"(_mbar), "r"(_par) : "memory");                                       \
    }                                                                                   \
} while (0)

#define TMA_LOAD2D(smem, map, cx, cy, mbar)                                             \
    asm volatile("cp.async.bulk.tensor.2d.shared::cta.global.tile.mbarrier::complete_tx::bytes " \
                 "[%0], [%1, {%2, %3}], [%4];"                                          \
                 :: "r"(smem), "l"(map), "r"(cx), "r"(cy), "r"(mbar) : "memory")

#define LDSM_X4(r0, r1, r2, r3, addr)                                                   \
    asm volatile("ldmatrix.sync.aligned.m8n8.x4.shared.b16 {%0,%1,%2,%3}, [%4];"        \
                 : "=r"(r0), "=r"(r1), "=r"(r2), "=r"(r3) : "r"(addr))

__device__ __forceinline__ void mma_f16(float c[4], uint32_t a0, uint32_t a1, uint32_t a2,
                                        uint32_t a3, uint32_t b0, uint32_t b1) {
    asm volatile(
        "mma.sync.aligned.m16n8k16.row.col.f32.f16.f16.f32 "
        "{%0,%1,%2,%3}, {%4,%5,%6,%7}, {%8,%9}, {%0,%1,%2,%3};"
        : "+f"(c[0]), "+f"(c[1]), "+f"(c[2]), "+f"(c[3])
        : "r"(a0), "r"(a1), "r"(a2), "r"(a3), "r"(b0), "r"(b1));
}

// ============================================================================
// Merged prep: dequant W -> fp16, convert X -> fp16 (one launch; R4-validated)
// ============================================================================
__device__ __forceinline__ uint32_t h2bits(float a, float b) {
    __half2 h = __floats2half2_rn(a, b);
    return *reinterpret_cast<uint32_t*>(&h);
}

#define W_BLOCKS ((DOUT * DIN / 8) / 256)   // 24576
#define X_BLOCKS ((MROWS * DIN / 8) / 256)  // 8192

__global__ void prep_kernel(const float4* __restrict__ x, const float4* __restrict__ peso,
                            const float* __restrict__ escala,
                            uint4* __restrict__ gX, uint4* __restrict__ gW) {
    const int bid = blockIdx.x;
    if (bid < W_BLOCKS) {
        int i = bid * 256 + threadIdx.x;
        int e   = i << 3;
        int row = e >> 12;            // / DIN
        int col = e & (DIN - 1);
        float s = __ldg(&escala[(row >> 7) * (DIN / 128) + (col >> 7)]);
        float4 v0 = peso[2 * i], v1 = peso[2 * i + 1];
        uint4 u;
        u.x = h2bits(v0.x * s, v0.y * s); u.y = h2bits(v0.z * s, v0.w * s);
        u.z = h2bits(v1.x * s, v1.y * s); u.w = h2bits(v1.z * s, v1.w * s);
        gW[i] = u;
    } else {
        int i = (bid - W_BLOCKS) * 256 + threadIdx.x;
        float4 v0 = x[2 * i], v1 = x[2 * i + 1];
        uint4 u;
        u.x = h2bits(v0.x, v0.y); u.y = h2bits(v0.z, v0.w);
        u.z = h2bits(v1.x, v1.y); u.w = h2bits(v1.z, v1.w);
        gX[i] = u;
    }
}

// ============================================================================
// GEMM: C[m,n] = sum_k X[m,k] * W[n,k]   (fp16 in, fp32 accum/out)
//   CTA 256x128, BK=64, 4-stage TMA ring, occ 1.
//   8 compute warps (4M x 2N grid, warp tile 64x64) + 1 TMA producer warp.
//   Fragment DOUBLE BUFFERING: ks+1's LDSMs issue before ks's MMAs, hiding
//   LDS latency inside a single warp (R4's binder at 2 warps/SMSP).
//   Swizzle key row&7 == iq for ALL fragment rows (16/64 multiples of 8).
// ============================================================================
__global__ void __launch_bounds__(NTHREADS, 1)
gemm_f16_kernel(const __grid_constant__ CUtensorMap tmA,
                const __grid_constant__ CUtensorMap tmB,
                float* __restrict__ out) {
    extern __shared__ char smem[];
    const uint32_t sb = smem_u32(smem);
    const int tid  = threadIdx.x;
    const int wid  = tid >> 5;
    const int lane = tid & 31;

    const int m0 = blockIdx.y * BM;
    const int n0 = blockIdx.x * BN;

    if (tid == 0) {
        for (int s = 0; s < STAGES; s++) {
            MBAR_INIT(sb + MBAR_FULL(s), 1);
            MBAR_INIT(sb + MBAR_EMPTY(s), NWARPS_C);
        }
    }
    __syncthreads();

    if (wid == NWARPS_C) {
        // ---------------- TMA producer warp ----------------
        if (elect_one()) {
            int s = 0, ph = 1;               // first STAGES empty-waits pass immediately
            for (int kt = 0; kt < KT; kt++) {
                MBAR_WAIT(sb + MBAR_EMPTY(s), ph);
                MBAR_EXPECT_TX(sb + MBAR_FULL(s), STAGE_BYTES);
                const uint32_t stg = sb + SMEM_DATA0 + s * STAGE_BYTES;
                TMA_LOAD2D(stg,           &tmA, kt * BK, m0, sb + MBAR_FULL(s));
                TMA_LOAD2D(stg + A_BYTES, &tmB, kt * BK, n0, sb + MBAR_FULL(s));
                if (s == STAGES - 1) { s = 0; ph ^= 1; } else { s++; }
            }
        }
        return;
    }

    // ---------------- compute warps: 4M x 2N grid, warp tile 64x64 ----------------
    const int warp_m = wid >> 1;         // 0..3 -> M offset 64*warp_m
    const int warp_n = wid & 1;          // 0..1 -> N offset 64*warp_n
    const int q  = lane >> 3;            // ldmatrix quad
    const int iq = lane & 7;

    const int a_rif  = ((q & 1) << 3) + iq;    // row within 16-row fragment
    const uint32_t a_csel = (uint32_t)(q >> 1); // 16B chunk select
    const int b_rif  = ((q >> 1) << 3) + iq;
    const uint32_t b_csel = (uint32_t)(q & 1);

    float c[4][8][4];
#pragma unroll
    for (int mf = 0; mf < 4; mf++)
#pragma unroll
        for (int nf = 0; nf < 8; nf++)
#pragma unroll
            for (int r = 0; r < 4; r++) c[mf][nf][r] = 0.0f;

    // row byte offsets (swizzle key is iq for every fragment row)
    uint32_t a_off[4], b_off[4];
#pragma unroll
    for (int mf = 0; mf < 4; mf++)
        a_off[mf] = (uint32_t)((warp_m * 64 + mf * 16 + a_rif) * 128);
#pragma unroll
    for (int p = 0; p < 4; p++)
        b_off[p] = (uint32_t)((warp_n * 64 + p * 16 + b_rif) * 128);

    uint32_t a[2][4][4], b[2][8][2];

    auto load_frags = [&](int ks, uint32_t (&af)[4][4], uint32_t (&bf)[8][2],
                          uint32_t As, uint32_t Bs) {
        const uint32_t xa = (((uint32_t)(2 * ks) + a_csel) ^ (uint32_t)iq) << 4;
        const uint32_t xb = (((uint32_t)(2 * ks) + b_csel) ^ (uint32_t)iq) << 4;
#pragma unroll
        for (int mf = 0; mf < 4; mf++)
            LDSM_X4(af[mf][0], af[mf][1], af[mf][2], af[mf][3], As + a_off[mf] + xa);
#pragma unroll
        for (int p = 0; p < 4; p++)
            LDSM_X4(bf[2 * p][0], bf[2 * p][1], bf[2 * p + 1][0], bf[2 * p + 1][1],
                    Bs + b_off[p] + xb);
    };

    int s = 0, ph = 0;
    for (int kt = 0; kt < KT; kt++) {
        MBAR_WAIT(sb + MBAR_FULL(s), ph);
        const uint32_t As = sb + SMEM_DATA0 + s * STAGE_BYTES;
        const uint32_t Bs = As + A_BYTES;

        load_frags(0, a[0], b[0], As, Bs);
#pragma unroll
        for (int ks = 0; ks < 4; ks++) {       // 4 x k16 per stage, double-buffered
            if (ks < 3) load_frags(ks + 1, a[(ks + 1) & 1], b[(ks + 1) & 1], As, Bs);
            uint32_t (&af)[4][4] = a[ks & 1];
            uint32_t (&bf)[8][2] = b[ks & 1];
#pragma unroll
            for (int mf = 0; mf < 4; mf++)
#pragma unroll
                for (int nf = 0; nf < 8; nf++)
                    mma_f16(c[mf][nf], af[mf][0], af[mf][1], af[mf][2], af[mf][3],
                            bf[nf][0], bf[nf][1]);
        }
        // Safe point: all this stage's LDSM results consumed by mma.sync.
        __syncwarp();
        if (lane == 0) MBAR_ARRIVE(sb + MBAR_EMPTY(s));
        if (s == STAGES - 1) { s = 0; ph ^= 1; } else { s++; }
    }

    // ---------------- epilogue: direct float2 stores ----------------
    const int g   = lane >> 2;
    const int tig = lane & 3;
#pragma unroll
    for (int mf = 0; mf < 4; mf++) {
        const int m = m0 + warp_m * 64 + mf * 16 + g;
#pragma unroll
        for (int nf = 0; nf < 8; nf++) {
            const int n = n0 + warp_n * 64 + nf * 8 + tig * 2;
            *reinterpret_cast<float2*>(&out[(size_t)m * DOUT + n]) =
                make_float2(c[mf][nf][0], c[mf][nf][1]);
            *reinterpret_cast<float2*>(&out[(size_t)(m + 8) * DOUT + n]) =
                make_float2(c[mf][nf][2], c[mf][nf][3]);
        }
    }
}

// ============================================================================
// Host launch
// ============================================================================
typedef CUresult (*PFN_encodeTiled)(CUtensorMap*, CUtensorMapDataType, cuuint32_t, void*,
                                    const cuuint64_t*, const cuuint64_t*, const cuuint32_t*,
                                    const cuuint32_t*, CUtensorMapInterleave, CUtensorMapSwizzle,
                                    CUtensorMapL2promotion, CUtensorMapFloatOOBfill);

static PFN_encodeTiled get_encode_fn() {
    void* fn = nullptr;
#if CUDART_VERSION >= 12050
    cudaDriverEntryPointQueryResult qr;
    cudaGetDriverEntryPointByVersion("cuTensorMapEncodeTiled", &fn, 12000, cudaEnableDefault, &qr);
#else
    cudaGetDriverEntryPoint("cuTensorMapEncodeTiled", &fn, cudaEnableDefault);
#endif
    return (PFN_encodeTiled)fn;
}

static void encode_2d_f16(PFN_encodeTiled enc, CUtensorMap* tm, void* ptr,
                          uint64_t d0, uint64_t d1, uint32_t b0, uint32_t b1) {
    cuuint64_t dims[2]    = {d0, d1};
    cuuint64_t strides[1] = {d0 * sizeof(__half)};
    cuuint32_t box[2]     = {b0, b1};
    cuuint32_t es[2]      = {1, 1};
    enc(tm, CU_TENSOR_MAP_DATA_TYPE_FLOAT16, 2, ptr, dims, strides, box, es,
        CU_TENSOR_MAP_INTERLEAVE_NONE, CU_TENSOR_MAP_SWIZZLE_128B,
        CU_TENSOR_MAP_L2_PROMOTION_L2_128B, CU_TENSOR_MAP_FLOAT_OOB_FILL_NONE);
}

extern "C" void kernel_launch(void* const* d_in, const int* in_sizes, int n_in,
                              void* d_out, int out_size) {
    const float* x      = (const float*)d_in[0];
    const float* peso   = (const float*)d_in[1];
    const float* escala = (const float*)d_in[2];
    float* out          = (float*)d_out;

    __half *gX = nullptr, *gW = nullptr;
    cudaGetSymbolAddress((void**)&gX, g_X16);
    cudaGetSymbolAddress((void**)&gW, g_W16);

    prep_kernel<<<W_BLOCKS + X_BLOCKS, 256>>>((const float4*)x, (const float4*)peso, escala,
                                              (uint4*)gX, (uint4*)gW);

    PFN_encodeTiled enc = get_encode_fn();
    CUtensorMap tmA, tmB;
    encode_2d_f16(enc, &tmA, gX, DIN, MROWS, BK, BM);   // box 64x256
    encode_2d_f16(enc, &tmB, gW, DIN, DOUT,  BK, BN);   // box 64x128

    static bool attr_set = false;
    if (!attr_set) {
        cudaFuncSetAttribute(gemm_f16_kernel, cudaFuncAttributeMaxDynamicSharedMemorySize,
                             SMEM_TOTAL);
        attr_set = true;
    }

    dim3 grid(DOUT / BN, MROWS / BM);   // 96 x 16
    gemm_f16_kernel<<<grid, NTHREADS, SMEM_TOTAL>>>(tmA, tmB, out);
}